// round 2
// baseline (speedup 1.0000x reference)
#include <cuda_runtime.h>

// Problem constants (fixed by setup_inputs)
#define BATCH 8
#define NPTS  4096
#define FEAT  3
#define KNN   20
#define KSW   32     // kernel-matrix width KS
#define KLIST 12     // per-lane candidate list capacity
#define ROWS_PER_BLOCK 8
#define THREADS 256

// Output layout (float32):
//   [0 .. B*N*K)                    : spirals_index as float
//   [B*N*K .. B*N*K + B*N*K*KS)     : adjweight
#define IDX_COUNT (BATCH * NPTS * KNN)

__global__ __launch_bounds__(THREADS)
void pai_knn_kernel(const float* __restrict__ x,
                    const float* __restrict__ kern,
                    float* __restrict__ out)
{
    extern __shared__ float4 sp[];   // NPTS entries: (x, y, z, ||p||^2)

    const int b    = blockIdx.x >> 9;               // 512 blocks per batch
    const int row0 = (blockIdx.x & 511) * ROWS_PER_BLOCK;
    const float* xb = x + (size_t)b * FEAT * NPTS;

    // Stage batch points into shared. xx = ((x0^2 + x1^2) + x2^2), plain
    // mul/add chain (matches XLA's elementwise square + sequential reduce).
    for (int t = threadIdx.x; t < NPTS; t += THREADS) {
        float a0 = xb[t];
        float a1 = xb[NPTS + t];
        float a2 = xb[2 * NPTS + t];
        float xx = __fadd_rn(__fadd_rn(__fmul_rn(a0, a0), __fmul_rn(a1, a1)),
                             __fmul_rn(a2, a2));
        sp[t] = make_float4(a0, a1, a2, xx);
    }
    __syncthreads();

    const int warp = threadIdx.x >> 5;
    const int lane = threadIdx.x & 31;
    const int i    = row0 + warp;

    const float4 pi  = sp[i];
    const float xxi  = pi.w;

    // Per-lane top-KLIST list of 64-bit keys, sorted descending.
    // key = (ordered_uint(pd) << 32) | (~j)  -> bigger key == better neighbor,
    // equal pd -> smaller index wins (matches jax.lax.top_k).
    unsigned long long lst[KLIST];
#pragma unroll
    for (int t = 0; t < KLIST; ++t) lst[t] = 0ull;

    unsigned int low = ~(unsigned int)lane;   // ~(jj*32+lane) tracked incrementally
    for (int jj = 0; jj < NPTS / 32; ++jj, low -= 32u) {
        float4 pj = sp[jj * 32 + lane];
        // dot over f: sequential FMA chain f=0,1,2 (XLA K=3 contraction order)
        float d  = fmaf(pi.z, pj.z, fmaf(pi.y, pj.y, __fmul_rn(pi.x, pj.x)));
        // Reference broadcast order: pd = RN( RN(-xx_j + 2d) - xx_i )
        //   (-xx[b,0,m] - inner[b,n,m]) - xx[b,0,n],  m=j (column), n=i (row).
        // 2*d exact => fmaf(2,d,-xxj) == RN(-xxj - inner) bit-for-bit.
        float pd = __fadd_rn(fmaf(2.0f, d, -pj.w), -xxi);

        unsigned int u = __float_as_uint(pd);
        u = u ^ (unsigned int)(((int)u >> 31) | 0x80000000);
        unsigned long long key = ((unsigned long long)u << 32) | low;

        if (key > lst[KLIST - 1]) {
            unsigned long long c = key;
#pragma unroll
            for (int t = 0; t < KLIST; ++t) {
                bool gt = c > lst[t];
                unsigned long long mx = gt ? c : lst[t];
                unsigned long long mn = gt ? lst[t] : c;
                lst[t] = mx;
                c = mn;
            }
        }
    }

    // Warp merge: pop the global top-KNN in order.
    int nb[KNN];
    int myj = 0;
#pragma unroll
    for (int kk = 0; kk < KNN; ++kk) {
        unsigned long long m = lst[0];
#pragma unroll
        for (int s = 16; s; s >>= 1) {
            unsigned long long o = __shfl_xor_sync(0xffffffffu, m, s);
            if (o > m) m = o;
        }
        if (lst[0] == m) {            // unique winner (keys unique)
#pragma unroll
            for (int t = 0; t < KLIST - 1; ++t) lst[t] = lst[t + 1];
            lst[KLIST - 1] = 0ull;
        }
        int j = (int)(~(unsigned int)m);   // recover j from low word
        nb[kk] = j;
        if (lane == kk) myj = j;
    }

    const int grow = b * NPTS + i;            // global row (b*N + i)

    // Output 1: spirals_index (as float), lanes 0..19 write one each.
    if (lane < KNN)
        out[(size_t)grow * KNN + lane] = (float)(b * NPTS + myj);

    // Output 2: adjweight. Lane = ks column; loop kk over neighbors.
    const float k0 = kern[lane];
    const float k1 = kern[KSW + lane];
    const float k2 = kern[2 * KSW + lane];
    const float4 p0 = sp[nb[0]];

    float w[KNN];
#pragma unroll
    for (int kk = 0; kk < KNN; ++kk) {
        float4 pj = sp[nb[kk]];
        float d0 = pj.x - p0.x;
        float d1 = pj.y - p0.y;
        float d2 = pj.z - p0.z;
        float v  = fmaf(d2, k2, fmaf(d1, k1, __fmul_rn(d0, k0)));
        if (kk == 0 && lane == 0) v = __fadd_rn(v, 1.0f);  // one_padding[0][0]
        w[kk] = v;
    }

    // _top_max over the k axis (per ks column == per lane)
    float s1 = 0.0f;
#pragma unroll
    for (int kk = 0; kk < KNN; ++kk) {
        float t = w[kk] > 0.0f ? w[kk] : 0.0f;
        w[kk] = t;
        s1 = __fadd_rn(s1, t);
    }
    const float den1 = __fadd_rn(s1, 1e-6f);
    float s2 = 0.0f;
#pragma unroll
    for (int kk = 0; kk < KNN; ++kk) {
        float t = __fdiv_rn(w[kk], den1);
        t = __fmul_rn(t, t);
        w[kk] = t;
        s2 = __fadd_rn(s2, t);
    }
    const float den2 = __fadd_rn(s2, 1e-6f);

    float* ow = out + IDX_COUNT + (size_t)grow * (KNN * KSW);
#pragma unroll
    for (int kk = 0; kk < KNN; ++kk) {
        float t = __fdiv_rn(w[kk], den2);
        ow[kk * KSW + lane] = (t > 0.1f) ? t : 0.0f;
    }
}

extern "C" void kernel_launch(void* const* d_in, const int* in_sizes, int n_in,
                              void* d_out, int out_size)
{
    const float* x    = (const float*)d_in[0];
    const float* kern = (const float*)d_in[1];
    // d_in[2] (one_padding) and d_in[3] (k) are compile-time constants here.

    (void)in_sizes; (void)n_in; (void)out_size;

    cudaFuncSetAttribute(pai_knn_kernel,
                         cudaFuncAttributeMaxDynamicSharedMemorySize,
                         NPTS * sizeof(float4));

    dim3 grid(BATCH * (NPTS / ROWS_PER_BLOCK));   // 4096 blocks
    pai_knn_kernel<<<grid, THREADS, NPTS * sizeof(float4)>>>(x, kern, (float*)d_out);
}

// round 3
// speedup vs baseline: 2.0434x; 2.0434x over previous
#include <cuda_runtime.h>
#include <math_constants.h>

// Problem constants (fixed by setup_inputs)
#define BATCH 8
#define NPTS  4096
#define FEAT  3
#define KNN   20
#define KSW   32     // kernel-matrix width KS
#define KLIST 10     // per-lane candidate list capacity (balls-in-bins safe)
#define ROWS_PER_BLOCK 8
#define THREADS 256

// Output layout (float32):
//   [0 .. B*N*K)                : spirals_index as float
//   [B*N*K .. B*N*K + B*N*K*KS) : adjweight
#define IDX_COUNT (BATCH * NPTS * KNN)

// Sorted-descending insert of (pd, j). Strict '>' places equal-pd later
// entries after earlier ones; within a lane j is scanned ascending, so
// equal-pd ordering matches jax.lax.top_k automatically.
__device__ __forceinline__ void insert10(float pd, int j,
                                         float (&lpd)[KLIST], int (&lj)[KLIST])
{
#pragma unroll
    for (int t = 0; t < KLIST; ++t) {
        bool sw   = pd > lpd[t];
        float fmx = sw ? pd : lpd[t];
        float fmn = sw ? lpd[t] : pd;
        int   jmx = sw ? j : lj[t];
        int   jmn = sw ? lj[t] : j;
        lpd[t] = fmx; lj[t] = jmx;
        pd = fmn;     j = jmn;
    }
}

__global__ __launch_bounds__(THREADS)
void pai_knn_kernel(const float* __restrict__ x,
                    const float* __restrict__ kern,
                    float* __restrict__ out)
{
    extern __shared__ float4 sp[];   // NPTS entries: (x, y, z, ||p||^2)

    const int b    = blockIdx.x >> 9;               // 512 blocks per batch
    const int row0 = (blockIdx.x & 511) * ROWS_PER_BLOCK;
    const float* xb = x + (size_t)b * FEAT * NPTS;

    // Stage batch points: xx = ((x0^2 + x1^2) + x2^2), plain mul/add chain
    // (matches XLA elementwise square + sequential reduce).
    for (int t = threadIdx.x; t < NPTS; t += THREADS) {
        float a0 = xb[t];
        float a1 = xb[NPTS + t];
        float a2 = xb[2 * NPTS + t];
        float xx = __fadd_rn(__fadd_rn(__fmul_rn(a0, a0), __fmul_rn(a1, a1)),
                             __fmul_rn(a2, a2));
        sp[t] = make_float4(a0, a1, a2, xx);
    }
    __syncthreads();

    const int warp = threadIdx.x >> 5;
    const int lane = threadIdx.x & 31;
    const int i    = row0 + warp;

    const float4 pi  = sp[i];
    const float nxxi = -pi.w;

    // Per-lane top-KLIST (pd desc, j asc on ties)
    float lpd[KLIST];
    int   lj [KLIST];
#pragma unroll
    for (int t = 0; t < KLIST; ++t) { lpd[t] = -CUDART_INF_F; lj[t] = 0x40000000; }

    // Main scan: 4 candidates per lane per iteration (j, j+32, j+64, j+96).
#pragma unroll 1
    for (int it = 0; it < NPTS / 128; ++it) {
        const int j0 = it * 128 + lane;
        const float lastpd = lpd[KLIST - 1];   // stale threshold (conservative)

        float4 p0 = sp[j0];
        float4 p1 = sp[j0 + 32];
        float4 p2 = sp[j0 + 64];
        float4 p3 = sp[j0 + 96];

        // pd = RN( RN(-xx_j + 2*dot) - xx_i ), dot = sequential FMA chain.
        float d0 = fmaf(pi.z, p0.z, fmaf(pi.y, p0.y, __fmul_rn(pi.x, p0.x)));
        float d1 = fmaf(pi.z, p1.z, fmaf(pi.y, p1.y, __fmul_rn(pi.x, p1.x)));
        float d2 = fmaf(pi.z, p2.z, fmaf(pi.y, p2.y, __fmul_rn(pi.x, p2.x)));
        float d3 = fmaf(pi.z, p3.z, fmaf(pi.y, p3.y, __fmul_rn(pi.x, p3.x)));
        float pd0 = __fadd_rn(fmaf(2.0f, d0, -p0.w), nxxi);
        float pd1 = __fadd_rn(fmaf(2.0f, d1, -p1.w), nxxi);
        float pd2 = __fadd_rn(fmaf(2.0f, d2, -p2.w), nxxi);
        float pd3 = __fadd_rn(fmaf(2.0f, d3, -p3.w), nxxi);

        // Tournament of 4 (ties -> smaller j wins, via operand orientation).
        bool s01 = pd1 > pd0;
        float wpd01 = s01 ? pd1 : pd0;  int wj01 = s01 ? j0 + 32 : j0;
        float xpd01 = s01 ? pd0 : pd1;  int xj01 = s01 ? j0 : j0 + 32;
        bool s23 = pd3 > pd2;
        float wpd23 = s23 ? pd3 : pd2;  int wj23 = s23 ? j0 + 96 : j0 + 64;
        float xpd23 = s23 ? pd2 : pd3;  int xj23 = s23 ? j0 + 64 : j0 + 96;
        bool sw  = wpd23 > wpd01;
        float wpd = sw ? wpd23 : wpd01; int wj = sw ? wj23 : wj01;
        float ypd = sw ? wpd01 : wpd23; int yj = sw ? wj01 : wj23;

        // Winner: unconditional insert (qualifies warp-wide ~always).
        insert10(wpd, wj, lpd, lj);

        // Losers: guarded (>= is conservative on ties -> exact).
        if (xpd01 >= lastpd) insert10(xpd01, xj01, lpd, lj);
        if (xpd23 >= lastpd) insert10(xpd23, xj23, lpd, lj);
        if (ypd   >= lastpd) insert10(ypd,   yj,   lpd, lj);
    }

    // Warp merge: pop global top-KNN in order (exact tie-break: pd desc, j asc).
    int nb[KNN];
    int myj = 0;
#pragma unroll
    for (int kk = 0; kk < KNN; ++kk) {
        float mpd = lpd[0];
        int   mj  = lj[0];
#pragma unroll
        for (int s = 16; s; s >>= 1) {
            float opd = __shfl_xor_sync(0xffffffffu, mpd, s);
            int   oj  = __shfl_xor_sync(0xffffffffu, mj,  s);
            bool take = (opd > mpd) || (opd == mpd && oj < mj);
            mpd = take ? opd : mpd;
            mj  = take ? oj  : mj;
        }
        if (lj[0] == mj) {               // owner lane pops (j unique per lane)
#pragma unroll
            for (int t = 0; t < KLIST - 1; ++t) { lpd[t] = lpd[t+1]; lj[t] = lj[t+1]; }
            lpd[KLIST - 1] = -CUDART_INF_F; lj[KLIST - 1] = 0x40000000;
        }
        nb[kk] = mj;
        if (lane == kk) myj = mj;
    }

    const int grow = b * NPTS + i;            // global row (b*N + i)

    // Output 1: spirals_index (as float), lanes 0..19 write one each.
    if (lane < KNN)
        out[(size_t)grow * KNN + lane] = (float)(b * NPTS + myj);

    // Output 2: adjweight. Lane = ks column; loop kk over neighbors.
    const float k0 = kern[lane];
    const float k1 = kern[KSW + lane];
    const float k2 = kern[2 * KSW + lane];
    const float4 q0 = sp[nb[0]];

    float w[KNN];
#pragma unroll
    for (int kk = 0; kk < KNN; ++kk) {
        float4 qj = sp[nb[kk]];
        float e0 = qj.x - q0.x;
        float e1 = qj.y - q0.y;
        float e2 = qj.z - q0.z;
        float v  = fmaf(e2, k2, fmaf(e1, k1, __fmul_rn(e0, k0)));
        if (kk == 0 && lane == 0) v = __fadd_rn(v, 1.0f);  // one_padding[0][0]
        w[kk] = v;
    }

    // _top_max over the k axis (per ks column == per lane)
    float s1 = 0.0f;
#pragma unroll
    for (int kk = 0; kk < KNN; ++kk) {
        float t = w[kk] > 0.0f ? w[kk] : 0.0f;
        w[kk] = t;
        s1 = __fadd_rn(s1, t);
    }
    const float den1 = __fadd_rn(s1, 1e-6f);
    float s2 = 0.0f;
#pragma unroll
    for (int kk = 0; kk < KNN; ++kk) {
        float t = __fdiv_rn(w[kk], den1);
        t = __fmul_rn(t, t);
        w[kk] = t;
        s2 = __fadd_rn(s2, t);
    }
    const float den2 = __fadd_rn(s2, 1e-6f);

    float* ow = out + IDX_COUNT + (size_t)grow * (KNN * KSW);
#pragma unroll
    for (int kk = 0; kk < KNN; ++kk) {
        float t = __fdiv_rn(w[kk], den2);
        ow[kk * KSW + lane] = (t > 0.1f) ? t : 0.0f;
    }
}

extern "C" void kernel_launch(void* const* d_in, const int* in_sizes, int n_in,
                              void* d_out, int out_size)
{
    const float* x    = (const float*)d_in[0];
    const float* kern = (const float*)d_in[1];

    (void)in_sizes; (void)n_in; (void)out_size;

    cudaFuncSetAttribute(pai_knn_kernel,
                         cudaFuncAttributeMaxDynamicSharedMemorySize,
                         NPTS * sizeof(float4));

    dim3 grid(BATCH * (NPTS / ROWS_PER_BLOCK));   // 4096 blocks
    pai_knn_kernel<<<grid, THREADS, NPTS * sizeof(float4)>>>(x, kern, (float*)d_out);
}

// round 4
// speedup vs baseline: 2.6215x; 1.2829x over previous
#include <cuda_runtime.h>
#include <math_constants.h>

#define BATCH 8
#define NPTS  4096
#define FEAT  3
#define KNN   20
#define KSW   32
#define ROWS_PER_BLOCK 16
#define THREADS 512
#define FULL 0xffffffffu

// Output layout (float32):
//   [0 .. B*N*K)                : spirals_index as float
//   [B*N*K .. B*N*K + B*N*K*KS) : adjweight
#define IDX_COUNT (BATCH * NPTS * KNN)

__global__ __launch_bounds__(THREADS, 2)
void pai_knn_kernel(const float* __restrict__ x,
                    const float* __restrict__ kern,
                    float* __restrict__ out)
{
    extern __shared__ float4 sp[];   // NPTS entries: (x, y, z, ||p||^2)

    const int b    = blockIdx.x >> 8;               // 256 blocks per batch
    const int row0 = (blockIdx.x & 255) * ROWS_PER_BLOCK;
    const float* xb = x + (size_t)b * FEAT * NPTS;

    // Stage batch points: xx = ((x0^2 + x1^2) + x2^2), plain mul/add chain
    // (matches XLA elementwise square + sequential reduce).
    for (int t = threadIdx.x; t < NPTS; t += THREADS) {
        float a0 = xb[t];
        float a1 = xb[NPTS + t];
        float a2 = xb[2 * NPTS + t];
        float xx = __fadd_rn(__fadd_rn(__fmul_rn(a0, a0), __fmul_rn(a1, a1)),
                             __fmul_rn(a2, a2));
        sp[t] = make_float4(a0, a1, a2, xx);
    }
    __syncthreads();

    const int warp = threadIdx.x >> 5;
    const int lane = threadIdx.x & 31;
    const int i    = row0 + warp;

    const float4 pi  = sp[i];
    const float nxxi = -pi.w;

    // Warp-distributed top-20: lane k (k<20) holds the k-th best (pd desc,
    // j asc on equal pd). Lanes 20..31 hold shifted-out garbage (harmless).
    float v   = -CUDART_INF_F;   // this lane's list entry value
    int   idx = 0x7FFFFFFF;      // this lane's list entry index
    float tv  = -CUDART_INF_F;   // threshold = lane 19's v (warp-uniform copy)

#pragma unroll 1
    for (int it = 0; it < NPTS / 128; ++it) {
        const int jb = it * 128;
        float4 p0 = sp[jb + lane];
        float4 p1 = sp[jb + 32 + lane];
        float4 p2 = sp[jb + 64 + lane];
        float4 p3 = sp[jb + 96 + lane];

        // pd = RN( RN(-xx_j + 2*dot) - xx_i ), dot = sequential FMA chain
        // (reference broadcast order; 2*dot exact so fmaf == RN(-xxj - inner)).
        float d0 = fmaf(pi.z, p0.z, fmaf(pi.y, p0.y, __fmul_rn(pi.x, p0.x)));
        float d1 = fmaf(pi.z, p1.z, fmaf(pi.y, p1.y, __fmul_rn(pi.x, p1.x)));
        float d2 = fmaf(pi.z, p2.z, fmaf(pi.y, p2.y, __fmul_rn(pi.x, p2.x)));
        float d3 = fmaf(pi.z, p3.z, fmaf(pi.y, p3.y, __fmul_rn(pi.x, p3.x)));
        float pd0 = __fadd_rn(fmaf(2.0f, d0, -p0.w), nxxi);
        float pd1 = __fadd_rn(fmaf(2.0f, d1, -p1.w), nxxi);
        float pd2 = __fadd_rn(fmaf(2.0f, d2, -p2.w), nxxi);
        float pd3 = __fadd_rn(fmaf(2.0f, d3, -p3.w), nxxi);

#pragma unroll
        for (int c = 0; c < 4; ++c) {
            float pdc = (c == 0) ? pd0 : (c == 1) ? pd1 : (c == 2) ? pd2 : pd3;
            // Conservative qualifier (>= admits exact ties; insert resolves).
            unsigned qm = __ballot_sync(FULL, pdc >= tv);
            while (qm) {                      // warp-uniform, usually empty
                const int s = __ffs(qm) - 1;
                qm &= qm - 1;
                const float pc = __shfl_sync(FULL, pdc, s);
                const int   jc = jb + c * 32 + s;

                // Distributed insertion (exact tie-break: pd desc, j asc).
                float vu = __shfl_up_sync(FULL, v,   1);
                int   iu = __shfl_up_sync(FULL, idx, 1);
                bool take = (pc > v) || (pc == v && jc < idx);
                unsigned bt = __ballot_sync(FULL, take) & 0xFFFFFu;
                if (bt) {
                    const int p = __ffs(bt) - 1;
                    if (take) {
                        bool at = (lane == p);
                        v   = at ? pc : vu;
                        idx = at ? jc : iu;
                    }
                    tv = __shfl_sync(FULL, v, 19);
                }
            }
        }
    }

    const int grow = b * NPTS + i;            // global row (b*N + i)

    // Output 1: spirals_index (as float); lane k<20 already holds the k-th.
    if (lane < KNN)
        out[(size_t)grow * KNN + lane] = (float)(b * NPTS + idx);

    // Broadcast the 20 neighbor indices to all lanes.
    int nb[KNN];
#pragma unroll
    for (int kk = 0; kk < KNN; ++kk)
        nb[kk] = __shfl_sync(FULL, idx, kk);

    // Output 2: adjweight. Lane = ks column; loop kk over neighbors.
    const float k0 = kern[lane];
    const float k1 = kern[KSW + lane];
    const float k2 = kern[2 * KSW + lane];
    const float4 q0 = sp[nb[0]];

    float w[KNN];
#pragma unroll
    for (int kk = 0; kk < KNN; ++kk) {
        float4 qj = sp[nb[kk]];
        float e0 = qj.x - q0.x;
        float e1 = qj.y - q0.y;
        float e2 = qj.z - q0.z;
        float vv = fmaf(e2, k2, fmaf(e1, k1, __fmul_rn(e0, k0)));
        if (kk == 0 && lane == 0) vv = __fadd_rn(vv, 1.0f);  // one_padding[0][0]
        w[kk] = vv;
    }

    // _top_max over the k axis (per ks column == per lane)
    float s1 = 0.0f;
#pragma unroll
    for (int kk = 0; kk < KNN; ++kk) {
        float t = w[kk] > 0.0f ? w[kk] : 0.0f;
        w[kk] = t;
        s1 = __fadd_rn(s1, t);
    }
    const float den1 = __fadd_rn(s1, 1e-6f);
    float s2 = 0.0f;
#pragma unroll
    for (int kk = 0; kk < KNN; ++kk) {
        float t = __fdiv_rn(w[kk], den1);
        t = __fmul_rn(t, t);
        w[kk] = t;
        s2 = __fadd_rn(s2, t);
    }
    const float den2 = __fadd_rn(s2, 1e-6f);

    float* ow = out + IDX_COUNT + (size_t)grow * (KNN * KSW);
#pragma unroll
    for (int kk = 0; kk < KNN; ++kk) {
        float t = __fdiv_rn(w[kk], den2);
        ow[kk * KSW + lane] = (t > 0.1f) ? t : 0.0f;
    }
}

extern "C" void kernel_launch(void* const* d_in, const int* in_sizes, int n_in,
                              void* d_out, int out_size)
{
    const float* x    = (const float*)d_in[0];
    const float* kern = (const float*)d_in[1];

    (void)in_sizes; (void)n_in; (void)out_size;

    cudaFuncSetAttribute(pai_knn_kernel,
                         cudaFuncAttributeMaxDynamicSharedMemorySize,
                         NPTS * sizeof(float4));

    dim3 grid(BATCH * (NPTS / ROWS_PER_BLOCK));   // 2048 blocks
    pai_knn_kernel<<<grid, THREADS, NPTS * sizeof(float4)>>>(x, kern, (float*)d_out);
}

// round 5
// speedup vs baseline: 2.7028x; 1.0310x over previous
#include <cuda_runtime.h>
#include <math_constants.h>

#define BATCH 8
#define NPTS  4096
#define KNN   20
#define KSW   32
#define ROWS_PER_BLOCK 32     // 16 warps x 2 rows
#define THREADS 512
#define FULL 0xffffffffu

#define IDX_COUNT (BATCH * NPTS * KNN)

// pd = RN( RN(-xx_j + 2*dot) - xx_i ), dot = sequential FMA chain over f.
// (reference broadcast order; 2*dot exact so fmaf == RN(-xxj - inner)).
__device__ __forceinline__ float pdist(const float4 pi, const float nxxi, const float4 pj)
{
    float d = fmaf(pi.z, pj.z, fmaf(pi.y, pj.y, __fmul_rn(pi.x, pj.x)));
    return __fadd_rn(fmaf(2.0f, d, -pj.w), nxxi);
}

// Full bitonic sort of 32 (v, j) pairs across the warp, descending by
// (v desc, j asc on ties). j values are distinct, so no full ties.
__device__ __forceinline__ void bitonic32(float& v, int& j, const int lane)
{
#pragma unroll
    for (int k = 2; k <= 32; k <<= 1) {
#pragma unroll
        for (int s = k >> 1; s > 0; s >>= 1) {
            float ov = __shfl_xor_sync(FULL, v, s);
            int   oj = __shfl_xor_sync(FULL, j, s);
            bool ob = (ov > v) || (ov == v && oj < j);   // other is better
            bool up = ((lane & k) == 0) == ((lane & s) == 0);
            if (up ? ob : !ob) { v = ov; j = oj; }
        }
    }
}

// Process one 32-candidate batch against a warp-distributed sorted top-20
// (lane t<20 holds t-th best). Exact tie-break (pd desc, j asc): candidates
// arrive in globally ascending j and insertion uses (pc>v)||(pc==v && jc<idx).
// tv (warp-uniform lane-19 value) may be stale-low: conservative, exact.
__device__ __forceinline__ void processBatch(const float pdc, const int jbase,
                                             float& v, int& idx, float& tv,
                                             const int lane)
{
    unsigned qm = __ballot_sync(FULL, pdc >= tv);
    while (qm) {
        const int s = __ffs(qm) - 1;
        qm &= qm - 1;
        const float pc = __shfl_sync(FULL, pdc, s);
        const int   jc = jbase + s;

        float vu = __shfl_up_sync(FULL, v,   1);
        int   iu = __shfl_up_sync(FULL, idx, 1);
        bool take = (pc > v) || (pc == v && jc < idx);
        unsigned bt = __ballot_sync(FULL, take) & 0xFFFFFu;
        if (bt) {
            const int p = __ffs(bt) - 1;
            if (take) {
                bool at = (lane == p);
                v   = at ? pc : vu;
                idx = at ? jc : iu;
            }
            tv = __shfl_sync(FULL, v, 19);
        }
    }
}

__device__ __forceinline__ void epilogue(const float4* __restrict__ sp,
                                         float* __restrict__ out,
                                         const float k0, const float k1, const float k2,
                                         const int b, const int i, const int idx,
                                         const int lane)
{
    const int grow = b * NPTS + i;

    // Output 1: spirals_index (as float); lane t<20 already holds the t-th.
    if (lane < KNN)
        out[(size_t)grow * KNN + lane] = (float)(b * NPTS + idx);

    int nb[KNN];
#pragma unroll
    for (int kk = 0; kk < KNN; ++kk)
        nb[kk] = __shfl_sync(FULL, idx, kk);

    const float4 q0 = sp[nb[0]];
    float w[KNN];
#pragma unroll
    for (int kk = 0; kk < KNN; ++kk) {
        float4 qj = sp[nb[kk]];
        float e0 = qj.x - q0.x;
        float e1 = qj.y - q0.y;
        float e2 = qj.z - q0.z;
        float vv = fmaf(e2, k2, fmaf(e1, k1, __fmul_rn(e0, k0)));
        if (kk == 0 && lane == 0) vv = __fadd_rn(vv, 1.0f);  // one_padding[0][0]
        w[kk] = vv;
    }

    // _top_max over the k axis (per ks column == per lane)
    float s1 = 0.0f;
#pragma unroll
    for (int kk = 0; kk < KNN; ++kk) {
        float t = w[kk] > 0.0f ? w[kk] : 0.0f;
        w[kk] = t;
        s1 = __fadd_rn(s1, t);
    }
    const float den1 = __fadd_rn(s1, 1e-6f);
    float s2 = 0.0f;
#pragma unroll
    for (int kk = 0; kk < KNN; ++kk) {
        float t = __fdiv_rn(w[kk], den1);
        t = __fmul_rn(t, t);
        w[kk] = t;
        s2 = __fadd_rn(s2, t);
    }
    const float den2 = __fadd_rn(s2, 1e-6f);

    float* ow = out + IDX_COUNT + (size_t)grow * (KNN * KSW);
#pragma unroll
    for (int kk = 0; kk < KNN; ++kk) {
        float t = __fdiv_rn(w[kk], den2);
        ow[kk * KSW + lane] = (t > 0.1f) ? t : 0.0f;
    }
}

__global__ __launch_bounds__(THREADS, 2)
void pai_knn_kernel(const float* __restrict__ x,
                    const float* __restrict__ kern,
                    float* __restrict__ out)
{
    extern __shared__ float4 sp[];   // NPTS entries: (x, y, z, ||p||^2)

    const int b    = blockIdx.x >> 7;               // 128 blocks per batch
    const int row0 = (blockIdx.x & 127) * ROWS_PER_BLOCK;
    const float* xb = x + (size_t)b * 3 * NPTS;

    // Stage batch points: xx = ((x0^2 + x1^2) + x2^2), plain mul/add chain.
    for (int t = threadIdx.x; t < NPTS; t += THREADS) {
        float a0 = xb[t];
        float a1 = xb[NPTS + t];
        float a2 = xb[2 * NPTS + t];
        float xx = __fadd_rn(__fadd_rn(__fmul_rn(a0, a0), __fmul_rn(a1, a1)),
                             __fmul_rn(a2, a2));
        sp[t] = make_float4(a0, a1, a2, xx);
    }
    __syncthreads();

    const int warp = threadIdx.x >> 5;
    const int lane = threadIdx.x & 31;
    const int iA   = row0 + warp;          // row A
    const int iB   = iA + 16;              // row B

    const float4 piA = sp[iA];  const float nxxiA = -piA.w;
    const float4 piB = sp[iB];  const float nxxiB = -piB.w;

    // ---- Peel candidates 0..127: bitonic seed on 0..31, ballot on the rest.
    {
        float4 p0 = sp[lane];
        float4 p1 = sp[32 + lane];
        float4 p2 = sp[64 + lane];
        float4 p3 = sp[96 + lane];

        float a0 = pdist(piA, nxxiA, p0), a1 = pdist(piA, nxxiA, p1);
        float a2 = pdist(piA, nxxiA, p2), a3 = pdist(piA, nxxiA, p3);
        float b0 = pdist(piB, nxxiB, p0), b1 = pdist(piB, nxxiB, p1);
        float b2 = pdist(piB, nxxiB, p2), b3 = pdist(piB, nxxiB, p3);

        float vA = a0; int idxA = lane;
        bitonic32(vA, idxA, lane);
        float tvA = __shfl_sync(FULL, vA, 19);
        processBatch(a1, 32, vA, idxA, tvA, lane);
        processBatch(a2, 64, vA, idxA, tvA, lane);
        processBatch(a3, 96, vA, idxA, tvA, lane);

        float vB = b0; int idxB = lane;
        bitonic32(vB, idxB, lane);
        float tvB = __shfl_sync(FULL, vB, 19);
        processBatch(b1, 32, vB, idxB, tvB, lane);
        processBatch(b2, 64, vB, idxB, tvB, lane);
        processBatch(b3, 96, vB, idxB, tvB, lane);

        // ---- Main scan: shared candidate loads serve both rows.
#pragma unroll 1
        for (int it = 1; it < NPTS / 128; ++it) {
            const int jb = it * 128;
            p0 = sp[jb + lane];
            p1 = sp[jb + 32 + lane];
            p2 = sp[jb + 64 + lane];
            p3 = sp[jb + 96 + lane];

            a0 = pdist(piA, nxxiA, p0); a1 = pdist(piA, nxxiA, p1);
            a2 = pdist(piA, nxxiA, p2); a3 = pdist(piA, nxxiA, p3);
            b0 = pdist(piB, nxxiB, p0); b1 = pdist(piB, nxxiB, p1);
            b2 = pdist(piB, nxxiB, p2); b3 = pdist(piB, nxxiB, p3);

            processBatch(a0, jb,      vA, idxA, tvA, lane);
            processBatch(a1, jb + 32, vA, idxA, tvA, lane);
            processBatch(a2, jb + 64, vA, idxA, tvA, lane);
            processBatch(a3, jb + 96, vA, idxA, tvA, lane);

            processBatch(b0, jb,      vB, idxB, tvB, lane);
            processBatch(b1, jb + 32, vB, idxB, tvB, lane);
            processBatch(b2, jb + 64, vB, idxB, tvB, lane);
            processBatch(b3, jb + 96, vB, idxB, tvB, lane);
        }

        const float k0 = kern[lane];
        const float k1 = kern[KSW + lane];
        const float k2 = kern[2 * KSW + lane];

        epilogue(sp, out, k0, k1, k2, b, iA, idxA, lane);
        epilogue(sp, out, k0, k1, k2, b, iB, idxB, lane);
    }
}

extern "C" void kernel_launch(void* const* d_in, const int* in_sizes, int n_in,
                              void* d_out, int out_size)
{
    const float* x    = (const float*)d_in[0];
    const float* kern = (const float*)d_in[1];

    (void)in_sizes; (void)n_in; (void)out_size;

    cudaFuncSetAttribute(pai_knn_kernel,
                         cudaFuncAttributeMaxDynamicSharedMemorySize,
                         NPTS * sizeof(float4));

    dim3 grid(BATCH * (NPTS / ROWS_PER_BLOCK));   // 1024 blocks
    pai_knn_kernel<<<grid, THREADS, NPTS * sizeof(float4)>>>(x, kern, (float*)d_out);
}